// round 16
// baseline (speedup 1.0000x reference)
#include <cuda_runtime.h>

#define Lg 2048
#define LMASK 2047
#define LSHIFT 11
#define NCELL (Lg * Lg)

#define R_OVER_5 0.5554f      /* 2.777 / 5 */
#define ETA 0.8f
#define ONE_MINUS_ETA 0.2f
#define GAMMA 0.8f
#define INV_K 2.0f            /* 1 / 0.5 */

// Tile geometry: 64 wide x 16 tall, 256 threads, 4 inner cells/thread (col-major)
#define TX 64
#define TY 16
// (upd,type) exchange: rows row0-1 .. row0+16 (18), cols col0-1 .. col0+64 (66)
#define UROWS 18
#define UCOLS 66
#define USTR  68
#define NHALO 164              /* ring cells */

// 13-point fused (plus∘plus) stencil from GLOBAL memory (L1/L2-resident).
__device__ __forceinline__ float profit_at(const int* __restrict__ t,
                                           int row, int col, int* t00_out)
{
    int r0  = row << LSHIFT;
    int rm1 = ((row - 1) & LMASK) << LSHIFT;
    int rp1 = ((row + 1) & LMASK) << LSHIFT;
    int rm2 = ((row - 2) & LMASK) << LSHIFT;
    int rp2 = ((row + 2) & LMASK) << LSHIFT;
    int cm1 = (col - 1) & LMASK;
    int cp1 = (col + 1) & LMASK;
    int cm2 = (col - 2) & LMASK;
    int cp2 = (col + 2) & LMASK;

    int t00  = __ldg(t + r0 + col);
    int orth = __ldg(t + r0 + cm1) + __ldg(t + r0 + cp1)
             + __ldg(t + rm1 + col) + __ldg(t + rp1 + col);
    int diag = __ldg(t + rm1 + cm1) + __ldg(t + rm1 + cp1)
             + __ldg(t + rp1 + cm1) + __ldg(t + rp1 + cp1);
    int far2 = __ldg(t + r0 + cm2) + __ldg(t + r0 + cp2)
             + __ldg(t + rm2 + col) + __ldg(t + rp2 + col);

    int S2 = 5 * t00 + 2 * (orth + diag) + far2;
    *t00_out = t00;
    return (float)S2 * R_OVER_5 - 5.0f * (float)t00;
}

__global__ __launch_bounds__(256) void spgg_fused(
    const int* __restrict__ type_tm,
    const int* __restrict__ type_t,
    const float4* __restrict__ Q,
    const int* __restrict__ ldir,
    const float* __restrict__ lprob,
    float4* __restrict__ Q_out,
    float* __restrict__ type_out,
    float* __restrict__ profit_out)
{
    __shared__ float2 s_ut  [UROWS * USTR];   // (upd, type-as-float)
    __shared__ int4   s_dir4 [256];           // 16x64 dirs
    __shared__ float4 s_prob4[256];           // 16x64 probs
    const int*   s_dir  = (const int*)s_dir4;
    const float* s_prob = (const float*)s_prob4;

    int tid  = threadIdx.x;
    int bx   = blockIdx.x & 31;    // 32 column tiles
    int by   = blockIdx.x >> 5;    // 128 row tiles
    int row0 = by * TY;
    int col0 = bx * TX;

    int tr0 = (tid >> 6) << 2;     // 0,4,8,12
    int tc  = tid & 63;

    // ---- Stage ldir/lprob to smem (coalesced; registers die immediately) ----
    {
        int r  = tid >> 4;
        int c4 = (tid & 15) << 2;
        int g  = ((row0 + r) << LSHIFT) | (col0 + c4);
        s_dir4 [tid] = __ldcs((const int4*)  (ldir  + g));
        s_prob4[tid] = __ldcs((const float4*)(lprob + g));
    }

    // ---- Phase A: profit (global stencil) + Q update, inner cells ----
    int gidx[4];
    #pragma unroll
    for (int j = 0; j < 4; j++) {
        int tr  = tr0 + j;
        int row = row0 + tr;
        int col = col0 + tc;
        int gi  = (row << LSHIFT) | col;
        gidx[j] = gi;

        int t00;
        float profit = profit_at(type_t, row, col, &t00);

        float4 q = __ldcs(Q + gi);
        int A = __ldg(type_tm + gi);
        int B = t00;
        float maxv = B ? fmaxf(q.z, q.w) : fmaxf(q.x, q.y);
        float old  = B ? (A ? q.w : q.y) : (A ? q.z : q.x);
        float upd  = ONE_MINUS_ETA * old + ETA * (profit + GAMMA * maxv);
        if (A == 0) { if (B == 0) q.x = upd; else q.y = upd; }
        else        { if (B == 0) q.z = upd; else q.w = upd; }

        s_ut[(tr + 1) * USTR + (tc + 1)] = make_float2(upd, (float)t00);
        __stcs(Q_out + gi, q);
        __stcs(profit_out + gi, profit);
    }

    // ---- Halo-ring cells (threads 0..163): upd+type into smem only ----
    if (tid < NHALO) {
        int h = tid, hr, hc;
        if (h < UCOLS)            { hr = 0;             hc = h;          }
        else if (h < 2 * UCOLS)   { hr = UROWS - 1;     hc = h - UCOLS;  }
        else { int s = h - 2 * UCOLS; hr = 1 + (s >> 1); hc = (s & 1) ? (UCOLS - 1) : 0; }
        int row = (row0 - 1 + hr) & LMASK;
        int col = (col0 - 1 + hc) & LMASK;
        int gi  = (row << LSHIFT) | col;

        int t00;
        float profit = profit_at(type_t, row, col, &t00);

        float4 q = __ldg(Q + gi);     // shared with neighbor tile's inner read -> keep in L2
        int A = __ldg(type_tm + gi);
        int B = t00;
        float maxv = B ? fmaxf(q.z, q.w) : fmaxf(q.x, q.y);
        float old  = B ? (A ? q.w : q.y) : (A ? q.z : q.x);
        float upd  = ONE_MINUS_ETA * old + ETA * (profit + GAMMA * maxv);

        s_ut[hr * USTR + hc] = make_float2(upd, (float)t00);
    }

    __syncthreads();   // the ONLY barrier

    // ---- Phase B: fermi entirely from smem (zero global loads) ----
    #pragma unroll
    for (int j = 0; j < 4; j++) {
        int tr = tr0 + j;

        int   d = s_dir [tr * 64 + tc];
        float p = s_prob[tr * 64 + tc];

        float2 me = s_ut[(tr + 1) * USTR + (tc + 1)];

        int ur, uc;
        if (d == 0)      { ur = tr + 1; uc = tc;     }   // col-1
        else if (d == 1) { ur = tr + 1; uc = tc + 2; }   // col+1
        else if (d == 2) { ur = tr;     uc = tc + 1; }   // row-1
        else             { ur = tr + 2; uc = tc + 1; }   // row+1

        float2 nb = s_ut[ur * USTR + uc];

        float W = 1.0f / (1.0f + __expf((me.x - nb.x) * INV_K));
        float out = (p <= W) ? nb.y : me.y;
        __stcs(type_out + gidx[j], out);
    }
}

// ---------------------------------------------------------------------------
// Launch: output layout = concat(Q_new[4N], type_t1[N], profit[N]) as float32
// ---------------------------------------------------------------------------
extern "C" void kernel_launch(void* const* d_in, const int* in_sizes, int n_in,
                              void* d_out, int out_size)
{
    const int*    type_tm = (const int*)   d_in[0];
    const int*    type_t  = (const int*)   d_in[1];
    const float4* Q       = (const float4*)d_in[2];
    const int*    ldir    = (const int*)   d_in[3];
    const float*  lprob   = (const float*) d_in[4];

    float* out        = (float*)d_out;
    float4* Q_out     = (float4*)out;                 // [0, 4N)
    float* type_out   = out + 4 * (size_t)NCELL;      // [4N, 5N)
    float* profit_out = out + 5 * (size_t)NCELL;      // [5N, 6N)

    const int blocks = (Lg / TX) * (Lg / TY);         // 4096

    spgg_fused<<<blocks, 256>>>(type_tm, type_t, Q, ldir, lprob,
                                Q_out, type_out, profit_out);
}

// round 17
// speedup vs baseline: 1.2332x; 1.2332x over previous
#include <cuda_runtime.h>

#define Lg 2048
#define LMASK 2047
#define LSHIFT 11
#define NCELL (Lg * Lg)

#define R_OVER_5 0.5554f      /* 2.777 / 5 */
#define ETA 0.8f
#define ONE_MINUS_ETA 0.2f
#define GAMMA 0.8f
#define INV_K 2.0f            /* 1 / 0.5 */

// Tile geometry: 64 wide x 16 tall, 256 threads, 4 inner cells/thread (col-major)
#define TX 64
#define TY 16
// type staging: rows row0-3 .. row0+18 (22), cols col0-4 .. col0+71 (76 = 19 int4)
#define TROWS 22
#define TV4   19               /* int4 per staged row */
#define TSTR4 20               /* padded stride in int4 */
#define TSTR  80               /* padded stride in ints */
// (upd,type) exchange: rows row0-1 .. row0+16 (18), cols col0-1 .. col0+64 (66)
#define UROWS 18
#define UCOLS 66
#define USTR  68
#define NHALO 164              /* ring cells */

__global__ __launch_bounds__(256) void spgg_fused(
    const int* __restrict__ type_tm,
    const int* __restrict__ type_t,
    const float4* __restrict__ Q,
    const int* __restrict__ ldir,
    const float* __restrict__ lprob,
    float4* __restrict__ Q_out,
    float* __restrict__ type_out,
    float* __restrict__ profit_out)
{
    __shared__ int4   s_type4[TROWS * TSTR4];
    __shared__ float2 s_ut   [UROWS * USTR];   // (upd, type-as-float)
    __shared__ int4   s_dir4 [256];            // 16x64 dirs
    __shared__ float4 s_prob4[256];            // 16x64 probs
    const int*   s_type = (const int*)s_type4;
    const int*   s_dir  = (const int*)s_dir4;
    const float* s_prob = (const float*)s_prob4;

    int tid  = threadIdx.x;
    int bx   = blockIdx.x & 31;    // 32 column tiles
    int by   = blockIdx.x >> 5;    // 128 row tiles
    int row0 = by * TY;
    int col0 = bx * TX;

    int tr0 = (tid >> 6) << 2;     // 0,4,8,12 (first of 4 rows)
    int tc  = tid & 63;

    // ---- Stage ldir/lprob to smem (coalesced; registers die here) ----
    {
        int r  = tid >> 4;
        int c4 = (tid & 15) << 2;
        int g  = ((row0 + r) << LSHIFT) | (col0 + c4);
        s_dir4 [tid] = __ldcs((const int4*)  (ldir  + g));
        s_prob4[tid] = __ldcs((const float4*)(lprob + g));
    }

    // ---- Issue type staging loads (int4, wrap-indexed) ----
    int4 stage[2];
    int  sidx[2];
    #pragma unroll
    for (int k = 0; k < 2; k++) {
        int idx = tid + k * 256;
        if (idx < TROWS * TV4) {
            int r  = idx / TV4;
            int c4 = idx - r * TV4;
            int gr = (row0 - 3 + r) & LMASK;
            int gc = (col0 - 4 + (c4 << 2)) & LMASK;
            stage[k] = __ldg((const int4*)(type_t + (gr << LSHIFT) + gc));
            sidx[k]  = r * TSTR4 + c4;
        } else sidx[k] = -1;
    }

    // ---- Prefetch inner-cell Q/tm (4 cells per thread, col-major mapping) ----
    int gidx[4];
    float4 qv[4];
    int av[4];
    #pragma unroll
    for (int j = 0; j < 4; j++) {
        int tr = tr0 + j;
        gidx[j] = ((row0 + tr) << LSHIFT) | (col0 + tc);
        qv[j] = __ldcs(Q + gidx[j]);
        av[j] = __ldg(type_tm + gidx[j]);
    }

    // ---- Prefetch halo-ring cell (threads 0..163) ----
    int hr = 0, hc = 0;
    float4 qh;
    int ah = 0;
    bool has_halo = (tid < NHALO);
    if (has_halo) {
        int h = tid;
        if (h < UCOLS)            { hr = 0;             hc = h;          }
        else if (h < 2 * UCOLS)   { hr = UROWS - 1;     hc = h - UCOLS;  }
        else { int s = h - 2 * UCOLS; hr = 1 + (s >> 1); hc = (s & 1) ? (UCOLS - 1) : 0; }
        int gr = (row0 - 1 + hr) & LMASK;
        int gc = (col0 - 1 + hc) & LMASK;
        int hg = (gr << LSHIFT) | gc;
        qh = __ldcs(Q + hg);
        ah = __ldg(type_tm + hg);
    }

    // ---- Complete type staging, sync ----
    #pragma unroll
    for (int k = 0; k < 2; k++)
        if (sidx[k] >= 0) s_type4[sidx[k]] = stage[k];
    __syncthreads();

    // ---- Phase 2: profit (13-pt stencil from smem) + Q update ----
    #pragma unroll
    for (int j = 0; j < 4; j++) {
        int tr = tr0 + j;
        const int* st = s_type + (tr + 3) * TSTR + (tc + 4);
        int t00  = st[0];
        int orth = st[-1] + st[1] + st[-TSTR] + st[TSTR];
        int diag = st[-TSTR - 1] + st[-TSTR + 1] + st[TSTR - 1] + st[TSTR + 1];
        int far2 = st[-2] + st[2] + st[-2 * TSTR] + st[2 * TSTR];
        int S2   = 5 * t00 + 2 * (orth + diag) + far2;
        float profit = (float)S2 * R_OVER_5 - 5.0f * (float)t00;

        float4 q = qv[j];
        int A = av[j], B = t00;
        float maxv = B ? fmaxf(q.z, q.w) : fmaxf(q.x, q.y);
        float old  = B ? (A ? q.w : q.y) : (A ? q.z : q.x);
        float upd  = ONE_MINUS_ETA * old + ETA * (profit + GAMMA * maxv);
        if (A == 0) { if (B == 0) q.x = upd; else q.y = upd; }
        else        { if (B == 0) q.z = upd; else q.w = upd; }

        s_ut[(tr + 1) * USTR + (tc + 1)] = make_float2(upd, (float)t00);
        __stcs(Q_out + gidx[j], q);
        __stcs(profit_out + gidx[j], profit);
    }

    // halo cells: ut coords (hr, hc) -> type coords (hr+2, hc+3)
    if (has_halo) {
        const int* st = s_type + (hr + 2) * TSTR + (hc + 3);
        int t00  = st[0];
        int orth = st[-1] + st[1] + st[-TSTR] + st[TSTR];
        int diag = st[-TSTR - 1] + st[-TSTR + 1] + st[TSTR - 1] + st[TSTR + 1];
        int far2 = st[-2] + st[2] + st[-2 * TSTR] + st[2 * TSTR];
        int S2   = 5 * t00 + 2 * (orth + diag) + far2;
        float profit = (float)S2 * R_OVER_5 - 5.0f * (float)t00;

        float4 q = qh;
        int A = ah, B = t00;
        float maxv = B ? fmaxf(q.z, q.w) : fmaxf(q.x, q.y);
        float old  = B ? (A ? q.w : q.y) : (A ? q.z : q.x);
        float upd  = ONE_MINUS_ETA * old + ETA * (profit + GAMMA * maxv);
        s_ut[hr * USTR + hc] = make_float2(upd, (float)t00);
    }
    __syncthreads();

    // ---- Phase 3: fermi from packed (upd,type) smem — 2 LDS.64 per cell ----
    #pragma unroll
    for (int j = 0; j < 4; j++) {
        int tr = tr0 + j;

        int   d = s_dir [tr * 64 + tc];
        float p = s_prob[tr * 64 + tc];

        float2 me = s_ut[(tr + 1) * USTR + (tc + 1)];

        int ur, uc;
        if (d == 0)      { ur = tr + 1; uc = tc;     }   // col-1
        else if (d == 1) { ur = tr + 1; uc = tc + 2; }   // col+1
        else if (d == 2) { ur = tr;     uc = tc + 1; }   // row-1
        else             { ur = tr + 2; uc = tc + 1; }   // row+1

        float2 nb = s_ut[ur * USTR + uc];

        float W = 1.0f / (1.0f + __expf((me.x - nb.x) * INV_K));
        float out = (p <= W) ? nb.y : me.y;
        __stcs(type_out + gidx[j], out);
    }
}

// ---------------------------------------------------------------------------
// Launch: output layout = concat(Q_new[4N], type_t1[N], profit[N]) as float32
// ---------------------------------------------------------------------------
extern "C" void kernel_launch(void* const* d_in, const int* in_sizes, int n_in,
                              void* d_out, int out_size)
{
    const int*    type_tm = (const int*)   d_in[0];
    const int*    type_t  = (const int*)   d_in[1];
    const float4* Q       = (const float4*)d_in[2];
    const int*    ldir    = (const int*)   d_in[3];
    const float*  lprob   = (const float*) d_in[4];

    float* out        = (float*)d_out;
    float4* Q_out     = (float4*)out;                 // [0, 4N)
    float* type_out   = out + 4 * (size_t)NCELL;      // [4N, 5N)
    float* profit_out = out + 5 * (size_t)NCELL;      // [5N, 6N)

    const int blocks = (Lg / TX) * (Lg / TY);         // 4096

    spgg_fused<<<blocks, 256>>>(type_tm, type_t, Q, ldir, lprob,
                                Q_out, type_out, profit_out);
}